// round 3
// baseline (speedup 1.0000x reference)
#include <cuda_runtime.h>
#include <cstdint>

#define BB 4
#define TT 1024
#define DD 768
#define LL 4
#define DFF 3072
#define VV 50257
#define NB 148
#define NT 512
#define NWARP (NB * (NT / 32))   // 2368 warps
#define WCOLS 128

// ---------------- scratch (static __device__, no allocations) ----------------
__device__ float g_kwm[DD];
__device__ float g_kbm;
__device__ float g_kmean[BB * TT];
__device__ float g_w[BB * TT];
__device__ float g_xpart[BB * 32 * DD];
__device__ float g_pA[96 * BB * DD];    // 294912 floats
__device__ float g_pB[96 * BB * DD];
__device__ __align__(16) float g_xn[BB * DD];

__device__ unsigned g_arrive;
__device__ unsigned g_phase;

__device__ __forceinline__ float warp_sum(float v) {
    #pragma unroll
    for (int o = 16; o; o >>= 1) v += __shfl_xor_sync(0xffffffffu, v, o);
    return v;
}

// grid-wide barrier: all NB blocks co-resident (148 blocks, 1/SM).
__device__ __forceinline__ void gsync() {
    __syncthreads();
    if (threadIdx.x == 0) {
        volatile unsigned* ph = &g_phase;
        unsigned gen = *ph;
        __threadfence();
        if (atomicAdd(&g_arrive, 1u) == NB - 1) {
            g_arrive = 0;
            __threadfence();
            *ph = gen + 1;
        } else {
            while (*ph == gen) { }
        }
        __threadfence();
    }
    __syncthreads();
}

// ---- skinny GEMM stage with fused input reduction ---------------------------
// Input x[b,k] is either xpart (32-chunk sum) or split-K partials of the
// previous GEMM (srcKCH chunks), with optional bias / exact GELU applied.
// Output: dst[(kch*4+b)*N + n] = sum over this k-chunk of x[b,k]*W[k,n].
__device__ __forceinline__ void gemm_stage(int srcXpart, const float* __restrict__ src,
                                           int srcKCH, const float* __restrict__ bias,
                                           int act, const float* __restrict__ W,
                                           int K, int N, int NC, int KC,
                                           float* __restrict__ dst, float* sA) {
    int blk = blockIdx.x, tid = threadIdx.x;
    int nblocks = NC * ((K / KC) / 2);
    if (blk < nblocks) {
        int nc = blk % NC;
        int kpair = blk / NC;
        for (int i = tid; i < 8 * KC; i += NT) {
            int sub = i / (4 * KC);
            int rem = i - sub * 4 * KC;
            int b = rem / KC, kk = rem - b * KC;
            int kg = (kpair * 2 + sub) * KC + kk;
            float v = 0.f;
            if (srcXpart) {
                #pragma unroll 8
                for (int c = 0; c < 32; c++)
                    v += g_xpart[(size_t)(b * 32 + c) * DD + kg];
            } else {
                #pragma unroll 8
                for (int kc = 0; kc < srcKCH; kc++)
                    v += src[((size_t)kc * BB + b) * K + kg];
            }
            if (bias) v += bias[kg];
            if (act) v = 0.5f * v * (1.0f + erff(v * 0.70710678118654752f));
            sA[(sub * 4 + b) * KC + kk] = v;
        }
        __syncthreads();
        int sub = tid >> 8;
        int n = nc * 256 + (tid & 255);
        int kch = kpair * 2 + sub;
        const float* Wp = W + (size_t)(kch * KC) * N + n;
        const float* a = sA + sub * 4 * KC;
        float a0 = 0.f, a1 = 0.f, a2 = 0.f, a3 = 0.f;
        #pragma unroll 8
        for (int kk = 0; kk < KC; kk++) {
            float w = Wp[(size_t)kk * N];
            a0 += a[kk] * w;
            a1 += a[KC + kk] * w;
            a2 += a[2 * KC + kk] * w;
            a3 += a[3 * KC + kk] * w;
        }
        size_t base = (size_t)kch * BB * N + n;
        dst[base]         = a0;
        dst[base + N]     = a1;
        dst[base + 2 * N] = a2;
        dst[base + 3 * N] = a3;
        __syncthreads();
    }
}

// =================== persistent kernel: everything but lm_head ===============
__global__ __launch_bounds__(NT, 1)
void k_main(const int* __restrict__ idx, const float* __restrict__ wte,
            const float* __restrict__ wpe, const float* __restrict__ lnw,
            const float* __restrict__ kw,  const float* __restrict__ kb,
            const float* __restrict__ vw,  const float* __restrict__ vb,
            const float* __restrict__ fcw, const float* __restrict__ pw) {
    __shared__ float sm[BB * DD];   // 12 KB, reused per stage
    __shared__ int   smi[32];
    int blk = blockIdx.x, tid = threadIdx.x;
    int lane = tid & 31, wid = tid >> 5;
    int gw = blk * (NT / 32) + wid;

    // S0: kwm[i] = mean_d kw0[i,d]; kbm = mean(kb0)
    for (int i = gw; i < DD; i += NWARP) {
        const float* row = kw + (size_t)i * DD;
        float s = 0.f;
        #pragma unroll
        for (int jj = 0; jj < DD / 32; jj++) s += row[lane + jj * 32];
        s = warp_sum(s);
        if (lane == 0) g_kwm[i] = s * (1.0f / DD);
    }
    if (gw == NWARP - 1) {
        float s = 0.f;
        #pragma unroll
        for (int jj = 0; jj < DD / 32; jj++) s += kb[lane + jj * 32];
        s = warp_sum(s);
        if (lane == 0) g_kbm = s * (1.0f / DD);
    }
    gsync();

    // S1: k_mean[b,t] = (wte[idx]+wpe[t]) . kwm + kbm   (warp per token)
    for (int i = tid; i < DD; i += NT) sm[i] = g_kwm[i];
    __syncthreads();
    for (int tok = gw; tok < BB * TT; tok += NWARP) {
        int t = tok & (TT - 1);
        const float* e = wte + (size_t)idx[tok] * DD;
        const float* p = wpe + (size_t)t * DD;
        float s = 0.f;
        #pragma unroll
        for (int jj = 0; jj < DD / 32; jj++) {
            int j = lane + jj * 32;
            s += (e[j] + p[j]) * sm[j];
        }
        s = warp_sum(s);
        if (lane == 0) g_kmean[tok] = s + g_kbm;
    }
    gsync();

    // S2: softmax over T of cos(k_mean), per batch (blocks 0..3)
    if (blk < BB) {
        float v0 = cosf(g_kmean[blk * TT + tid]);
        float v1 = cosf(g_kmean[blk * TT + tid + 512]);
        sm[tid] = fmaxf(v0, v1); __syncthreads();
        for (int o = 256; o; o >>= 1) { if (tid < o) sm[tid] = fmaxf(sm[tid], sm[tid + o]); __syncthreads(); }
        float mx = sm[0]; __syncthreads();
        float e0 = expf(v0 - mx), e1 = expf(v1 - mx);
        sm[tid] = e0 + e1; __syncthreads();
        for (int o = 256; o; o >>= 1) { if (tid < o) sm[tid] += sm[tid + o]; __syncthreads(); }
        float inv = 1.0f / sm[0];
        g_w[blk * TT + tid]       = e0 * inv;
        g_w[blk * TT + tid + 512] = e1 * inv;
    }
    gsync();

    // S3: xbar partials (blocks 0..127: b = blk>>5, 32-token chunk c = blk&31)
    if (blk < 128) {
        int b = blk >> 5, c = blk & 31;
        if (tid < 32) {
            int t = c * 32 + tid;
            sm[tid]  = g_w[b * TT + t];
            smi[tid] = idx[b * TT + t];
        }
        __syncthreads();
        for (int d = tid; d < DD; d += NT) {
            float acc = 0.f;
            #pragma unroll 8
            for (int j = 0; j < 32; j++) {
                int t = c * 32 + j;
                acc += sm[j] * (wte[(size_t)smi[j] * DD + d] + wpe[(size_t)t * DD + d]);
            }
            g_xpart[(size_t)blk * DD + d] = acc;
        }
    }
    gsync();

    // 4 layers: ctx = x@vw+vb ; h = gelu(ctx@fcw) ; x = h@pw
    // Ping-pong partial buffers; reductions fused into consumer loads.
    float* P[2] = {g_pA, g_pB};
    int xb = -1;  // -1: x lives in g_xpart; else index of buffer holding x-partials
    for (int l = 0; l < LL; l++) {
        const float* vwl  = vw  + (size_t)l * DD * DD;
        const float* vbl  = vb  + (size_t)l * DD;
        const float* fcwl = fcw + (size_t)l * DD * DFF;
        const float* pwl  = pw  + (size_t)l * DFF * DD;

        float* d0 = (xb == 1) ? P[0] : ((xb == 0) ? P[1] : P[0]);
        float* d1 = (d0 == P[0]) ? P[1] : P[0];
        const float* xsrc = (xb < 0) ? nullptr : P[xb];

        // ctx-partials = x @ vw        (x reduced from xpart or pw-partials)
        gemm_stage(xb < 0, xsrc, 96, nullptr, 0, vwl, DD, DD, 3, 8, d0, sm);
        gsync();
        // h-partials = (ctx+vb) @ fcw
        gemm_stage(0, d0, 96, vbl, 0, fcwl, DD, DFF, 12, 32, d1, sm);
        gsync();
        // x-partials = gelu(h) @ pw
        gemm_stage(0, d1, 24, nullptr, 1, pwl, DFF, DD, 3, 32, d0, sm);
        gsync();
        xb = (d0 == P[0]) ? 0 : 1;
    }

    // ln_f on (B,D) state reduced from final partials (blocks 0..3)
    if (blk < BB) {
        const float* Px = P[xb];
        float v0 = 0.f, v1 = 0.f;
        #pragma unroll 8
        for (int kc = 0; kc < 96; kc++)
            v0 += Px[((size_t)kc * BB + blk) * DD + tid];
        if (tid < 256) {
            #pragma unroll 8
            for (int kc = 0; kc < 96; kc++)
                v1 += Px[((size_t)kc * BB + blk) * DD + tid + 512];
        }
        sm[tid] = v0 + v1; __syncthreads();
        for (int o = 256; o; o >>= 1) { if (tid < o) sm[tid] += sm[tid + o]; __syncthreads(); }
        float mu = sm[0] * (1.0f / DD); __syncthreads();
        float d0 = v0 - mu, d1 = (tid < 256) ? (v1 - mu) : 0.f;
        sm[tid] = d0 * d0 + ((tid < 256) ? d1 * d1 : 0.f); __syncthreads();
        for (int o = 256; o; o >>= 1) { if (tid < o) sm[tid] += sm[tid + o]; __syncthreads(); }
        float rstd = rsqrtf(sm[0] * (1.0f / DD) + 1e-5f);
        g_xn[blk * DD + tid] = d0 * rstd * lnw[tid];
        if (tid < 256) g_xn[blk * DD + tid + 512] = d1 * rstd * lnw[tid + 512];
    }
}

// ========== fused lm_head + broadcast: out[b,t,v] = xn[b,:].wte[v,:] =========
// Block = 128-vocab-column window. Phase A: compute rl[4][128] from wte.
// Phase B: per-warp constant alignment phase (row*VV mod 4 == row mod 4 and
// rows r == warp mod 8) -> payload lives in registers, one STG.128 per row.
__global__ __launch_bounds__(256)
void k_bcast(const float* __restrict__ wte, float* __restrict__ out) {
    __shared__ float4 sxn4[BB * DD / 4];   // 12 KB
    __shared__ float rl[BB][WCOLS];        // 2 KB
    int tid = threadIdx.x, warp = tid >> 5, lane = tid & 31;
    int w0 = blockIdx.x * WCOLS;
    int ncol = VV - w0; if (ncol > WCOLS) ncol = WCOLS;

    for (int i = tid; i < BB * DD / 4; i += 256)
        sxn4[i] = ((const float4*)g_xn)[i];
    __syncthreads();

    // Phase A: logits for this window (warp per vocab row)
    for (int ci = warp; ci < ncol; ci += 8) {
        const float4* wr = (const float4*)(wte + (size_t)(w0 + ci) * DD);
        float a0 = 0.f, a1 = 0.f, a2 = 0.f, a3 = 0.f;
        #pragma unroll
        for (int jj = 0; jj < DD / 128; jj++) {
            int j = lane + jj * 32;
            float4 w = wr[j];
            float4 x0 = sxn4[j];
            float4 x1 = sxn4[192 + j];
            float4 x2 = sxn4[384 + j];
            float4 x3 = sxn4[576 + j];
            a0 += w.x * x0.x + w.y * x0.y + w.z * x0.z + w.w * x0.w;
            a1 += w.x * x1.x + w.y * x1.y + w.z * x1.z + w.w * x1.w;
            a2 += w.x * x2.x + w.y * x2.y + w.z * x2.z + w.w * x2.w;
            a3 += w.x * x3.x + w.y * x3.y + w.z * x3.z + w.w * x3.w;
        }
        a0 = warp_sum(a0); a1 = warp_sum(a1); a2 = warp_sum(a2); a3 = warp_sum(a3);
        if (lane == 0) { rl[0][ci] = a0; rl[1][ci] = a1; rl[2][ci] = a2; rl[3][ci] = a3; }
    }
    __syncthreads();

    // Phase B: broadcast
    if (ncol == WCOLS) {
        int p = (4 - (warp & 3)) & 3;          // constant per warp
        int nv = (WCOLS - p) >> 2;             // 32 (p=0) or 31
        int rem = p ? (4 - p) : 0;
        #pragma unroll
        for (int b = 0; b < BB; b++) {
            int si = p + 4 * lane;
            float4 v;
            if (lane < nv) v = make_float4(rl[b][si], rl[b][si + 1], rl[b][si + 2], rl[b][si + 3]);
            float hv = (lane < p)   ? rl[b][lane] : 0.f;
            float tv = (lane < rem) ? rl[b][p + 4 * nv + lane] : 0.f;
            for (int r = warp; r < TT; r += 8) {
                float* dst = out + (size_t)(b * TT + r) * VV + w0;
                if (lane < p)  dst[lane] = hv;
                if (lane < nv) __stcs((float4*)(dst + p) + lane, v);
                if (lane < rem) dst[p + 4 * nv + lane] = tv;
            }
        }
    } else {
        // last (partial) window: scalar path
        for (int b = 0; b < BB; b++) {
            for (int r = warp; r < TT; r += 8) {
                float* dst = out + (size_t)(b * TT + r) * VV + w0;
                for (int c = lane; c < ncol; c += 32) dst[c] = rl[b][c];
            }
        }
    }
}

// ---------------- launch ------------------------------------------------------
extern "C" void kernel_launch(void* const* d_in, const int* in_sizes, int n_in,
                              void* d_out, int out_size) {
    const int*   idx = (const int*)  d_in[0];
    const float* wte = (const float*)d_in[1];
    const float* wpe = (const float*)d_in[2];
    const float* lnw = (const float*)d_in[3];
    // d_in[4]=qw, d_in[5]=qb : dead (scores independent of Q)
    const float* kw  = (const float*)d_in[6];
    const float* kb  = (const float*)d_in[7];
    const float* vw  = (const float*)d_in[8];
    const float* vb  = (const float*)d_in[9];
    const float* fcw = (const float*)d_in[10];
    const float* pw  = (const float*)d_in[11];
    float* out = (float*)d_out;

    k_main<<<NB, NT>>>(idx, wte, wpe, lnw, kw, kb, vw, vb, fcw, pw);
    k_bcast<<<(VV + WCOLS - 1) / WCOLS, 256>>>(wte, out);
}